// round 9
// baseline (speedup 1.0000x reference)
#include <cuda_runtime.h>
#include <cstdint>

// ---------------- problem dims ----------------
#define NTOK 4096
#define CDIM 1024
#define ENUM 8
#define HDIM 512
#define HSDIM 2048

// ---------------- GEMM tiling ----------------
#define BM 128
#define BK 32
#define AST 48                        // smem row stride: 48 mod 32 = 16 -> conflict-free LDS.128
#define STG (BM * AST)                // 6144 floats = 24KB per operand stage
#define SMEMB (4 * STG * 4)           // 98304 B (2 stages x (A+B))

// p16 permutation within each 16-wide k-group: storage order
// [0,4,8,12, 1,5,9,13, 2,6,10,14, 3,7,11,15]
// storage pos of logical c (0..15): (c&3)*4 + (c>>2)
__device__ __forceinline__ int p16(int c) { return ((c & 3) << 2) | ((c >> 2) & 3); }

// ---------------- device scratch ----------------
__device__ int   d_cnt[ENUM];
__device__ int   d_tok[ENUM][NTOK];
__device__ float d_gate[ENUM][NTOK];
__device__ int   d_eslot[NTOK][2];
__device__ float d_hid [ENUM*NTOK*HDIM];    // p16 tf32 hidden
__device__ float d_pair[ENUM*NTOK*CDIM];    // gate-scaled expert out (canonical)
__device__ float d_sh  [NTOK*HSDIM];        // p16 tf32 shared hidden
__device__ float d_xr  [NTOK*CDIM];         // p16 tf32 x
__device__ float d_guT [ENUM*2*HDIM*CDIM];  // [E][2H][C] transposed, p16
__device__ float d_dwT [ENUM*CDIM*HDIM];    // [E][C][H] transposed, p16
__device__ float d_sgwr[HSDIM*CDIM];        // p16
__device__ float d_suwr[HSDIM*CDIM];        // p16
__device__ float d_sdwr[CDIM*HSDIM];        // p16

// ---------------- helpers ----------------
__device__ __forceinline__ float tf32r(float f) {
    uint32_t u; asm("cvt.rna.tf32.f32 %0, %1;" : "=r"(u) : "f"(f));
    return __uint_as_float(u);
}
__device__ __forceinline__ void cp16(float* s, const float* g) {
    uint32_t sa = (uint32_t)__cvta_generic_to_shared(s);
    asm volatile("cp.async.cg.shared.global [%0], [%1], 16;" :: "r"(sa), "l"(g));
}
__device__ __forceinline__ void mma8(float* d, const uint32_t* a, const uint32_t* b) {
    asm volatile(
        "mma.sync.aligned.m16n8k8.row.col.f32.tf32.tf32.f32 "
        "{%0,%1,%2,%3},{%4,%5,%6,%7},{%8,%9},{%0,%1,%2,%3};"
        : "+f"(d[0]), "+f"(d[1]), "+f"(d[2]), "+f"(d[3])
        : "r"(a[0]), "r"(a[1]), "r"(a[2]), "r"(a[3]), "r"(b[0]), "r"(b[1]));
}
__device__ __forceinline__ float silu_f(float v) { return v / (1.f + expf(-v)); }

// ---------------- router: logits/top2/gates + writes p16 tf32 x -----------------
__global__ void router_kernel(const float* __restrict__ x, const float* __restrict__ rw,
                              float* __restrict__ xw) {
    int t = blockIdx.x * (blockDim.x >> 5) + (threadIdx.x >> 5);
    int lane = threadIdx.x & 31;
    if (t >= NTOK) return;
    const float* xr = x + (long long)t * CDIM;
    float* xo = xw + (long long)t * CDIM;
    float acc[ENUM];
#pragma unroll
    for (int e = 0; e < ENUM; e++) acc[e] = 0.f;
    for (int i = lane; i < CDIM; i += 32) {
        float xv = xr[i];
        xo[(i & ~15) | p16(i & 15)] = tf32r(xv);
#pragma unroll
        for (int e = 0; e < ENUM; e++) acc[e] += xv * rw[e * CDIM + i];
    }
#pragma unroll
    for (int e = 0; e < ENUM; e++)
#pragma unroll
        for (int off = 16; off; off >>= 1) acc[e] += __shfl_xor_sync(~0u, acc[e], off);
    if (lane == 0) {
        int i0 = 0; float v0 = acc[0];
#pragma unroll
        for (int e = 1; e < ENUM; e++) if (acc[e] > v0) { v0 = acc[e]; i0 = e; }
        int i1 = -1; float v1 = -3.0e38f;
#pragma unroll
        for (int e = 0; e < ENUM; e++) if (e != i0 && acc[e] > v1) { v1 = acc[e]; i1 = e; }
        float g0 = 1.f / (1.f + expf(-v0));
        float g1 = 1.f / (1.f + expf(-v1));
        int s0 = atomicAdd(&d_cnt[i0], 1);
        int s1 = atomicAdd(&d_cnt[i1], 1);
        d_tok[i0][s0] = t; d_gate[i0][s0] = g0; d_eslot[t][0] = i0 * NTOK + s0;
        d_tok[i1][s1] = t; d_gate[i1][s1] = g1; d_eslot[t][1] = i1 * NTOK + s1;
    }
}

// ---------------- preprocessing ----------------
// round + p16 permute: each thread handles one 16-float k-group (a 4x4 transpose)
__global__ void round_perm3(const float* __restrict__ s0, float* __restrict__ d0,
                            const float* __restrict__ s1, float* __restrict__ d1,
                            const float* __restrict__ s2, float* __restrict__ d2) {
    const float* src = (blockIdx.y == 0) ? s0 : (blockIdx.y == 1) ? s1 : s2;
    float*       dst = (blockIdx.y == 0) ? d0 : (blockIdx.y == 1) ? d1 : d2;
    long long g = (long long)blockIdx.x * 256 + threadIdx.x;
    float4 a = ((const float4*)src)[g * 4];
    float4 b = ((const float4*)src)[g * 4 + 1];
    float4 c = ((const float4*)src)[g * 4 + 2];
    float4 d = ((const float4*)src)[g * 4 + 3];
    ((float4*)dst)[g * 4]     = make_float4(tf32r(a.x), tf32r(b.x), tf32r(c.x), tf32r(d.x));
    ((float4*)dst)[g * 4 + 1] = make_float4(tf32r(a.y), tf32r(b.y), tf32r(c.y), tf32r(d.y));
    ((float4*)dst)[g * 4 + 2] = make_float4(tf32r(a.z), tf32r(b.z), tf32r(c.z), tf32r(d.z));
    ((float4*)dst)[g * 4 + 3] = make_float4(tf32r(a.w), tf32r(b.w), tf32r(c.w), tf32r(d.w));
}
// dst[z][c][perm16(r)] = rna(src[z][r][c])
__global__ void transpose_rna_perm(const float* __restrict__ src, float* __restrict__ dst,
                                   int R, int C) {
    __shared__ float tile[32][33];
    long long zo = (long long)blockIdx.z * R * C;
    int r0 = blockIdx.y * 32, c0 = blockIdx.x * 32;
    int tx = threadIdx.x, ty = threadIdx.y;
#pragma unroll
    for (int i = 0; i < 32; i += 8)
        tile[ty + i][tx] = src[zo + (long long)(r0 + ty + i) * C + c0 + tx];
    __syncthreads();
    int rp = r0 + (tx & 16) + p16(tx & 15);
#pragma unroll
    for (int i = 0; i < 32; i += 8)
        dst[zo + (long long)(c0 + ty + i) * R + rp] = tf32r(tile[tx][ty + i]);
}

// ---------------- phase 1: fused SwiGLU GEMMs -----------------------------------
// CTA: 128 threads (2x2 warps). Tile: 128 rows x 64 hidden cols.
// smem B: 64 gate rows + 64 up rows. Warp: 64 rows x 32 cols, dual G/U accums.
__global__ __launch_bounds__(128) void phase1_kernel(
    const float* __restrict__ xr, const float* __restrict__ guT,
    const float* __restrict__ sgw, const float* __restrict__ suw,
    float* __restrict__ hid, float* __restrict__ sh)
{
    const int bid = blockIdx.x;
    const float *B1, *B2;
    float* C; int ldc, z = 0, bm, bn; bool gather;
    if (bid < 2048) {
        z = bid >> 8; int rem = bid & 255; bm = rem >> 3; bn = rem & 7;
        if (bm * BM >= d_cnt[z]) return;
        gather = true;
        B1 = guT + (long long)z * 2 * HDIM * CDIM + (long long)(bn * 64) * CDIM;
        B2 = B1 + (long long)HDIM * CDIM;
        C  = hid + (long long)z * NTOK * HDIM;
        ldc = HDIM;
    } else {
        int s = bid - 2048; bm = s >> 5; bn = s & 31;
        gather = false;
        B1 = sgw + (long long)(bn * 64) * CDIM;
        B2 = suw + (long long)(bn * 64) * CDIM;
        C  = sh;
        ldc = HSDIM;
    }
    const int K = CDIM;

    extern __shared__ __align__(16) float smem[];
    float* sA = smem;                   // [2][128][AST]
    float* sB = smem + 2 * STG;         // [2][128][AST]  rows 0-63 gate, 64-127 up

    const int tid = threadIdx.x, lane = tid & 31, w = tid >> 5;
    const int ly = lane >> 2, lx = lane & 3;
    const int wm = w >> 1, wn = w & 1;  // 2 x 2 warps

    const float* aPtr[8];
    const float* bPtr[8];
    const int rbase = tid >> 3, kc = (tid & 7) * 4;
#pragma unroll
    for (int c = 0; c < 8; c++) {
        int row = rbase + 16 * c;
        long long arow = gather ? (long long)d_tok[z][bm * BM + row] : (long long)(bm * BM + row);
        aPtr[c] = xr + arow * K;
        bPtr[c] = ((row < 64) ? (B1 + (long long)row * K) : (B2 + (long long)(row - 64) * K));
    }
    auto loadStage = [&](int st, int k0) {
        float* dA = sA + st * STG;
        float* dB = sB + st * STG;
#pragma unroll
        for (int c = 0; c < 8; c++) {
            int row = rbase + 16 * c;
            cp16(dA + row * AST + kc, aPtr[c] + k0 + kc);
            cp16(dB + row * AST + kc, bPtr[c] + k0 + kc);
        }
        asm volatile("cp.async.commit_group;");
    };

    float accG[4][4][4], accU[4][4][4];
#pragma unroll
    for (int a = 0; a < 4; a++)
#pragma unroll
        for (int b = 0; b < 4; b++)
#pragma unroll
            for (int q = 0; q < 4; q++) { accG[a][b][q] = 0.f; accU[a][b][q] = 0.f; }

    const int nk = K / BK;
    loadStage(0, 0);

    for (int kt = 0; kt < nk; kt++) {
        const int st = kt & 1;
        asm volatile("cp.async.wait_group 0;");
        __syncthreads();
        if (kt + 1 < nk) loadStage((kt + 1) & 1, (kt + 1) * BK);

        const float* cA = sA + st * STG;
        const float* cB = sB + st * STG;
#pragma unroll
        for (int g = 0; g < 2; g++) {       // two 16-wide k-groups per K-tile
            const int kb = g * 16;
            float4 a0[4], a1[4], bg4[4], bu4[4];
#pragma unroll
            for (int im = 0; im < 4; im++) {
                int r = wm * 64 + im * 16;
                a0[im] = *(const float4*)(cA + (r     + ly) * AST + kb + 4 * lx);
                a1[im] = *(const float4*)(cA + (r + 8 + ly) * AST + kb + 4 * lx);
            }
#pragma unroll
            for (int in = 0; in < 4; in++) {
                int cn = wn * 32 + in * 8 + ly;
                bg4[in] = *(const float4*)(cB + cn * AST + kb + 4 * lx);
                bu4[in] = *(const float4*)(cB + (64 + cn) * AST + kb + 4 * lx);
            }
            // ks sub-slice 0: k = {lx, lx+4}
#pragma unroll
            for (int im = 0; im < 4; im++) {
                uint32_t af[4] = { __float_as_uint(a0[im].x), __float_as_uint(a1[im].x),
                                   __float_as_uint(a0[im].y), __float_as_uint(a1[im].y) };
#pragma unroll
                for (int in = 0; in < 4; in++) {
                    uint32_t bg[2] = { __float_as_uint(bg4[in].x), __float_as_uint(bg4[in].y) };
                    uint32_t bu[2] = { __float_as_uint(bu4[in].x), __float_as_uint(bu4[in].y) };
                    mma8(accG[im][in], af, bg);
                    mma8(accU[im][in], af, bu);
                }
            }
            // ks sub-slice 1: k = {8+lx, 12+lx}
#pragma unroll
            for (int im = 0; im < 4; im++) {
                uint32_t af[4] = { __float_as_uint(a0[im].z), __float_as_uint(a1[im].z),
                                   __float_as_uint(a0[im].w), __float_as_uint(a1[im].w) };
#pragma unroll
                for (int in = 0; in < 4; in++) {
                    uint32_t bg[2] = { __float_as_uint(bg4[in].z), __float_as_uint(bg4[in].w) };
                    uint32_t bu[2] = { __float_as_uint(bu4[in].z), __float_as_uint(bu4[in].w) };
                    mma8(accG[im][in], af, bg);
                    mma8(accU[im][in], af, bu);
                }
            }
        }
    }

    // epilogue: out = rna(silu(g)*u), stored p16 (consumed as GEMM k-dim next)
    // logical col L = in*8 + 2lx (+1); group base (in>>1)*16; pos(L), pos(L+1)=pos(L)+4
#pragma unroll
    for (int im = 0; im < 4; im++) {
        int rr = bm * BM + wm * 64 + im * 16 + ly;
#pragma unroll
        for (int in = 0; in < 4; in++) {
            int l = ((in & 1) << 3) | (lx << 1);
            int pos = p16(l);
            long long gbase = (long long)rr * ldc + bn * 64 + wn * 32 + (in >> 1) * 16;
            float* g = accG[im][in];
            float* u = accU[im][in];
            C[gbase + pos]                     = tf32r(silu_f(g[0]) * u[0]);
            C[gbase + pos + 4]                 = tf32r(silu_f(g[1]) * u[1]);
            C[gbase + 8LL * ldc + pos]         = tf32r(silu_f(g[2]) * u[2]);
            C[gbase + 8LL * ldc + pos + 4]     = tf32r(silu_f(g[3]) * u[3]);
        }
    }
}

// ---------------- phase 2: down GEMMs -------------------------------------------
// CTA: 128 threads (2x2 warps). Tile: 128 x 128. Warp: 64 x 64.
__global__ __launch_bounds__(128) void phase2_kernel(
    const float* __restrict__ hid, const float* __restrict__ dwT,
    const float* __restrict__ sh,  const float* __restrict__ sdw,
    float* __restrict__ pair, float* __restrict__ out)
{
    const int bid = blockIdx.x;
    const float *A, *B; const float* gate; float* C;
    int K, z = 0, bm, bn;
    if (bid < 2048) {
        z = bid >> 8; int rem = bid & 255; bm = rem >> 3; bn = rem & 7;
        if (bm * BM >= d_cnt[z]) return;
        A = hid + (long long)z * NTOK * HDIM;
        K = HDIM;
        B = dwT + (long long)z * CDIM * HDIM + (long long)(bn * 128) * HDIM;
        C = pair + (long long)z * NTOK * CDIM;
        gate = d_gate[z];
    } else {
        int s = bid - 2048; bm = s >> 3; bn = s & 7;
        A = sh; K = HSDIM;
        B = sdw + (long long)(bn * 128) * HSDIM;
        C = out;
        gate = nullptr;
    }

    extern __shared__ __align__(16) float smem[];
    float* sA = smem;                   // [2][128][AST]
    float* sB = smem + 2 * STG;         // [2][128][AST]

    const int tid = threadIdx.x, lane = tid & 31, w = tid >> 5;
    const int ly = lane >> 2, lx = lane & 3;
    const int wm = w >> 1, wn = w & 1;  // 2 x 2 warps, each 64x64

    const int rbase = tid >> 3, kc = (tid & 7) * 4;
    const float* aBase = A + (long long)(bm * BM + rbase) * K;
    const float* bBase = B + (long long)rbase * K;

    auto loadStage = [&](int st, int k0) {
        float* dA = sA + st * STG;
        float* dB = sB + st * STG;
#pragma unroll
        for (int c = 0; c < 8; c++) {
            int row = rbase + 16 * c;
            cp16(dA + row * AST + kc, aBase + (long long)(16 * c) * K + k0 + kc);
            cp16(dB + row * AST + kc, bBase + (long long)(16 * c) * K + k0 + kc);
        }
        asm volatile("cp.async.commit_group;");
    };

    float acc[4][8][4];
#pragma unroll
    for (int a = 0; a < 4; a++)
#pragma unroll
        for (int b = 0; b < 8; b++)
#pragma unroll
            for (int q = 0; q < 4; q++) acc[a][b][q] = 0.f;

    const int nk = K / BK;
    loadStage(0, 0);

    for (int kt = 0; kt < nk; kt++) {
        const int st = kt & 1;
        asm volatile("cp.async.wait_group 0;");
        __syncthreads();
        if (kt + 1 < nk) loadStage((kt + 1) & 1, (kt + 1) * BK);

        const float* cA = sA + st * STG;
        const float* cB = sB + st * STG;
#pragma unroll
        for (int g = 0; g < 2; g++) {
            const int kb = g * 16;
            float4 a0[4], a1[4], bb[8];
#pragma unroll
            for (int im = 0; im < 4; im++) {
                int r = wm * 64 + im * 16;
                a0[im] = *(const float4*)(cA + (r     + ly) * AST + kb + 4 * lx);
                a1[im] = *(const float4*)(cA + (r + 8 + ly) * AST + kb + 4 * lx);
            }
#pragma unroll
            for (int in = 0; in < 8; in++) {
                int cn = wn * 64 + in * 8 + ly;
                bb[in] = *(const float4*)(cB + cn * AST + kb + 4 * lx);
            }
#pragma unroll
            for (int im = 0; im < 4; im++) {
                uint32_t af[4] = { __float_as_uint(a0[im].x), __float_as_uint(a1[im].x),
                                   __float_as_uint(a0[im].y), __float_as_uint(a1[im].y) };
#pragma unroll
                for (int in = 0; in < 8; in++) {
                    uint32_t bf[2] = { __float_as_uint(bb[in].x), __float_as_uint(bb[in].y) };
                    mma8(acc[im][in], af, bf);
                }
            }
#pragma unroll
            for (int im = 0; im < 4; im++) {
                uint32_t af[4] = { __float_as_uint(a0[im].z), __float_as_uint(a1[im].z),
                                   __float_as_uint(a0[im].w), __float_as_uint(a1[im].w) };
#pragma unroll
                for (int in = 0; in < 8; in++) {
                    uint32_t bf[2] = { __float_as_uint(bb[in].z), __float_as_uint(bb[in].w) };
                    mma8(acc[im][in], af, bf);
                }
            }
        }
    }

    // epilogue (canonical layout, float2 stores)
#pragma unroll
    for (int im = 0; im < 4; im++) {
        int rr = bm * BM + wm * 64 + im * 16 + ly;
        float s0 = gate ? gate[rr] : 1.f;
        float s1 = gate ? gate[rr + 8] : 1.f;
#pragma unroll
        for (int in = 0; in < 8; in++) {
            long long base = (long long)rr * CDIM + bn * 128 + wn * 64 + in * 8 + lx * 2;
            *(float2*)(C + base)              = make_float2(acc[im][in][0] * s0, acc[im][in][1] * s0);
            *(float2*)(C + base + 8LL * CDIM) = make_float2(acc[im][in][2] * s1, acc[im][in][3] * s1);
        }
    }
}

// ---------------- final combine: out += gated expert pair ----------------
__global__ void combine_kernel(float* __restrict__ out) {
    long long i = (long long)blockIdx.x * 256 + threadIdx.x;
    int t = (int)(i >> 8), j = (int)(i & 255);
    int es0 = d_eslot[t][0], es1 = d_eslot[t][1];
    float4 o  = ((float4*)out)[i];
    float4 p0 = ((const float4*)d_pair)[(long long)es0 * 256 + j];
    float4 p1 = ((const float4*)d_pair)[(long long)es1 * 256 + j];
    o.x += p0.x + p1.x; o.y += p0.y + p1.y;
    o.z += p0.z + p1.z; o.w += p0.w + p1.w;
    ((float4*)out)[i] = o;
}

// ---------------- launch ----------------
extern "C" void kernel_launch(void* const* d_in, const int* in_sizes, int n_in,
                              void* d_out, int out_size) {
    const float* x   = (const float*)d_in[0];
    const float* rw  = (const float*)d_in[1];
    const float* guw = (const float*)d_in[2];
    const float* dw  = (const float*)d_in[3];
    const float* sgw = (const float*)d_in[4];
    const float* suw = (const float*)d_in[5];
    const float* sdw = (const float*)d_in[6];
    float* out = (float*)d_out;

    void* a;
    float *p_hid, *p_pair, *p_sh, *p_xr, *p_guT, *p_dwT, *p_sgwr, *p_suwr, *p_sdwr;
    cudaGetSymbolAddress(&a, d_hid);  p_hid  = (float*)a;
    cudaGetSymbolAddress(&a, d_pair); p_pair = (float*)a;
    cudaGetSymbolAddress(&a, d_sh);   p_sh   = (float*)a;
    cudaGetSymbolAddress(&a, d_xr);   p_xr   = (float*)a;
    cudaGetSymbolAddress(&a, d_guT);  p_guT  = (float*)a;
    cudaGetSymbolAddress(&a, d_dwT);  p_dwT  = (float*)a;
    cudaGetSymbolAddress(&a, d_sgwr); p_sgwr = (float*)a;
    cudaGetSymbolAddress(&a, d_suwr); p_suwr = (float*)a;
    cudaGetSymbolAddress(&a, d_sdwr); p_sdwr = (float*)a;
    void* cntAddr; cudaGetSymbolAddress(&cntAddr, d_cnt);
    cudaMemsetAsync(cntAddr, 0, sizeof(int) * ENUM);

    cudaFuncSetAttribute(phase1_kernel, cudaFuncAttributeMaxDynamicSharedMemorySize, SMEMB);
    cudaFuncSetAttribute(phase2_kernel, cudaFuncAttributeMaxDynamicSharedMemorySize, SMEMB);

    // router (also emits p16 tf32 x) + weight preprocessing
    router_kernel<<<NTOK / 8, 256>>>(x, rw, p_xr);
    round_perm3<<<dim3(HSDIM * CDIM / 16 / 256, 3), 256>>>(sgw, p_sgwr, suw, p_suwr, sdw, p_sdwr);
    transpose_rna_perm<<<dim3(2 * HDIM / 32, CDIM / 32, ENUM), dim3(32, 8)>>>(guw, p_guT, CDIM, 2 * HDIM);
    transpose_rna_perm<<<dim3(CDIM / 32, HDIM / 32, ENUM), dim3(32, 8)>>>(dw, p_dwT, HDIM, CDIM);

    // phase 1: expert gate_up (2048 CTAs) + shared gate/up (1024 CTAs), fused SwiGLU
    phase1_kernel<<<3072, 128, SMEMB>>>(p_xr, p_guT, p_sgwr, p_suwr, p_hid, p_sh);

    // phase 2: expert down gate-scaled (2048 CTAs) + shared down (256 CTAs)
    phase2_kernel<<<2304, 128, SMEMB>>>(p_hid, p_dwT, p_sh, p_sdwr, p_pair, out);

    // out += gated expert pair
    combine_kernel<<<NTOK * CDIM / 4 / 256, 256>>>(out);

    (void)in_sizes; (void)n_in; (void)out_size;
}

// round 10
// speedup vs baseline: 1.1847x; 1.1847x over previous
#include <cuda_runtime.h>
#include <cstdint>

// ---------------- problem dims ----------------
#define NTOK 4096
#define CDIM 1024
#define ENUM 8
#define HDIM 512
#define HSDIM 2048

// ---------------- GEMM tiling (round-8 proven config) ----------------
#define BM 128
#define BK 32
#define AST 40                        // smem row stride: bank stride 8 -> conflict-free LDS.64
#define STG (BM * AST)                // 5120 floats = 20KB per operand stage
#define SMEMB (4 * STG * 4)           // 81920 B (2 stages x (A+B))

// k-pair permutation within each 8-wide k-group: storage order [0,4,1,5,2,6,3,7]
__device__ __forceinline__ int pk8(int c) { return ((c & 3) << 1) | ((c >> 2) & 1); }

// ---------------- device scratch ----------------
__device__ int   d_cnt[ENUM];
__device__ int   d_tok[ENUM][NTOK];
__device__ float d_gate[ENUM][NTOK];
__device__ int   d_eslot[NTOK][2];
__device__ float d_hid [ENUM*NTOK*HDIM];    // k-paired tf32 hidden
__device__ float d_pair[ENUM*NTOK*CDIM];    // gate-scaled expert out (canonical)
__device__ float d_sh  [NTOK*HSDIM];        // k-paired tf32 shared hidden
__device__ float d_xr  [NTOK*CDIM];         // k-paired tf32 x
__device__ float d_guT [ENUM*2*HDIM*CDIM];  // [E][2H][C] transposed, k-paired
__device__ float d_dwT [ENUM*CDIM*HDIM];    // [E][C][H] transposed, k-paired
__device__ float d_sgwr[HSDIM*CDIM];        // k-paired
__device__ float d_suwr[HSDIM*CDIM];        // k-paired
__device__ float d_sdwr[CDIM*HSDIM];        // k-paired

// ---------------- helpers ----------------
__device__ __forceinline__ float tf32r(float f) {
    uint32_t u; asm("cvt.rna.tf32.f32 %0, %1;" : "=r"(u) : "f"(f));
    return __uint_as_float(u);
}
__device__ __forceinline__ void cp16(float* s, const float* g) {
    uint32_t sa = (uint32_t)__cvta_generic_to_shared(s);
    asm volatile("cp.async.cg.shared.global [%0], [%1], 16;" :: "r"(sa), "l"(g));
}
__device__ __forceinline__ void mma8(float* d, const uint32_t* a, const uint32_t* b) {
    asm volatile(
        "mma.sync.aligned.m16n8k8.row.col.f32.tf32.tf32.f32 "
        "{%0,%1,%2,%3},{%4,%5,%6,%7},{%8,%9},{%0,%1,%2,%3};"
        : "+f"(d[0]), "+f"(d[1]), "+f"(d[2]), "+f"(d[3])
        : "r"(a[0]), "r"(a[1]), "r"(a[2]), "r"(a[3]), "r"(b[0]), "r"(b[1]));
}
__device__ __forceinline__ float silu_f(float v) { return v / (1.f + expf(-v)); }

// ---------------- router: logits/top2/gates + writes k-paired tf32 x ------------
__global__ void router_kernel(const float* __restrict__ x, const float* __restrict__ rw,
                              float* __restrict__ xw) {
    int t = blockIdx.x * (blockDim.x >> 5) + (threadIdx.x >> 5);
    int lane = threadIdx.x & 31;
    if (t >= NTOK) return;
    const float* xr = x + (long long)t * CDIM;
    float* xo = xw + (long long)t * CDIM;
    float acc[ENUM];
#pragma unroll
    for (int e = 0; e < ENUM; e++) acc[e] = 0.f;
    for (int i = lane; i < CDIM; i += 32) {
        float xv = xr[i];
        xo[(i & ~7) | pk8(i & 7)] = tf32r(xv);
#pragma unroll
        for (int e = 0; e < ENUM; e++) acc[e] += xv * rw[e * CDIM + i];
    }
#pragma unroll
    for (int e = 0; e < ENUM; e++)
#pragma unroll
        for (int off = 16; off; off >>= 1) acc[e] += __shfl_xor_sync(~0u, acc[e], off);
    if (lane == 0) {
        int i0 = 0; float v0 = acc[0];
#pragma unroll
        for (int e = 1; e < ENUM; e++) if (acc[e] > v0) { v0 = acc[e]; i0 = e; }
        int i1 = -1; float v1 = -3.0e38f;
#pragma unroll
        for (int e = 0; e < ENUM; e++) if (e != i0 && acc[e] > v1) { v1 = acc[e]; i1 = e; }
        float g0 = 1.f / (1.f + expf(-v0));
        float g1 = 1.f / (1.f + expf(-v1));
        int s0 = atomicAdd(&d_cnt[i0], 1);
        int s1 = atomicAdd(&d_cnt[i1], 1);
        d_tok[i0][s0] = t; d_gate[i0][s0] = g0; d_eslot[t][0] = i0 * NTOK + s0;
        d_tok[i1][s1] = t; d_gate[i1][s1] = g1; d_eslot[t][1] = i1 * NTOK + s1;
    }
}

// ---------------- preprocessing ----------------
__global__ void round_perm3(const float* __restrict__ s0, float* __restrict__ d0,
                            const float* __restrict__ s1, float* __restrict__ d1,
                            const float* __restrict__ s2, float* __restrict__ d2) {
    const float* src = (blockIdx.y == 0) ? s0 : (blockIdx.y == 1) ? s1 : s2;
    float*       dst = (blockIdx.y == 0) ? d0 : (blockIdx.y == 1) ? d1 : d2;
    long long g = (long long)blockIdx.x * 256 + threadIdx.x;
    float4 a = ((const float4*)src)[g * 2];
    float4 b = ((const float4*)src)[g * 2 + 1];
    ((float4*)dst)[g * 2]     = make_float4(tf32r(a.x), tf32r(b.x), tf32r(a.y), tf32r(b.y));
    ((float4*)dst)[g * 2 + 1] = make_float4(tf32r(a.z), tf32r(b.z), tf32r(a.w), tf32r(b.w));
}
// dst[z][c][perm(r)] = rna(src[z][r][c])
__global__ void transpose_rna_perm(const float* __restrict__ src, float* __restrict__ dst,
                                   int R, int C) {
    __shared__ float tile[32][33];
    long long zo = (long long)blockIdx.z * R * C;
    int r0 = blockIdx.y * 32, c0 = blockIdx.x * 32;
    int tx = threadIdx.x, ty = threadIdx.y;
#pragma unroll
    for (int i = 0; i < 32; i += 8)
        tile[ty + i][tx] = src[zo + (long long)(r0 + ty + i) * C + c0 + tx];
    __syncthreads();
    int rp = r0 + ((tx & ~7) | pk8(tx & 7));
#pragma unroll
    for (int i = 0; i < 32; i += 8)
        dst[zo + (long long)(c0 + ty + i) * R + rp] = tf32r(tile[tx][ty + i]);
}

// ---------------- phase 1: fused SwiGLU GEMMs (templated expert/shared) ---------
// CTA: 128 threads (2x2 warps). Tile: 128 rows x 64 hidden cols.
template <bool EXPERT>
__global__ __launch_bounds__(128) void phase1_kernel(
    const float* __restrict__ xr, const float* __restrict__ guT,
    const float* __restrict__ sgw, const float* __restrict__ suw,
    float* __restrict__ hid, float* __restrict__ sh)
{
    const int bid = blockIdx.x;
    const float *B1, *B2;
    float* C; int ldc, z = 0, bm, bn;
    if (EXPERT) {
        z = bid >> 8; int rem = bid & 255; bm = rem >> 3; bn = rem & 7;
        if (bm * BM >= d_cnt[z]) return;
        B1 = guT + (long long)z * 2 * HDIM * CDIM + (long long)(bn * 64) * CDIM;
        B2 = B1 + (long long)HDIM * CDIM;
        C  = hid + (long long)z * NTOK * HDIM;
        ldc = HDIM;
    } else {
        bm = bid >> 5; bn = bid & 31;
        B1 = sgw + (long long)(bn * 64) * CDIM;
        B2 = suw + (long long)(bn * 64) * CDIM;
        C  = sh;
        ldc = HSDIM;
    }
    const int K = CDIM;

    extern __shared__ __align__(16) float smem[];
    float* sA = smem;                   // [2][128][AST]
    float* sB = smem + 2 * STG;         // [2][128][AST]  rows 0-63 gate, 64-127 up

    const int tid = threadIdx.x, lane = tid & 31, w = tid >> 5;
    const int ly = lane >> 2, lx = lane & 3;
    const int wm = w >> 1, wn = w & 1;  // 2 x 2 warps

    const float* aPtr[8];
    const float* bPtr[8];
    const int rbase = tid >> 3, kc = (tid & 7) * 4;
#pragma unroll
    for (int c = 0; c < 8; c++) {
        int row = rbase + 16 * c;
        long long arow = EXPERT ? (long long)d_tok[z][bm * BM + row] : (long long)(bm * BM + row);
        aPtr[c] = xr + arow * K;
        bPtr[c] = ((row < 64) ? (B1 + (long long)row * K) : (B2 + (long long)(row - 64) * K));
    }
    auto loadStage = [&](int st, int k0) {
        float* dA = sA + st * STG;
        float* dB = sB + st * STG;
#pragma unroll
        for (int c = 0; c < 8; c++) {
            int row = rbase + 16 * c;
            cp16(dA + row * AST + kc, aPtr[c] + k0 + kc);
            cp16(dB + row * AST + kc, bPtr[c] + k0 + kc);
        }
        asm volatile("cp.async.commit_group;");
    };

    float accG[4][4][4], accU[4][4][4];
#pragma unroll
    for (int a = 0; a < 4; a++)
#pragma unroll
        for (int b = 0; b < 4; b++)
#pragma unroll
            for (int q = 0; q < 4; q++) { accG[a][b][q] = 0.f; accU[a][b][q] = 0.f; }

    const int nk = K / BK;
    loadStage(0, 0);

    for (int kt = 0; kt < nk; kt++) {
        const int st = kt & 1;
        asm volatile("cp.async.wait_group 0;");
        __syncthreads();
        if (kt + 1 < nk) loadStage((kt + 1) & 1, (kt + 1) * BK);

        const float* cA = sA + st * STG;
        const float* cB = sB + st * STG;
#pragma unroll
        for (int ks = 0; ks < 4; ks++) {
            const int kb = ks * 8;
            uint32_t af[4][4], bg[4][2], bu[4][2];
#pragma unroll
            for (int im = 0; im < 4; im++) {
                int r = wm * 64 + im * 16;
                float2 v0 = *(const float2*)(cA + (r     + ly) * AST + kb + 2 * lx);
                float2 v1 = *(const float2*)(cA + (r + 8 + ly) * AST + kb + 2 * lx);
                af[im][0] = __float_as_uint(v0.x); af[im][2] = __float_as_uint(v0.y);
                af[im][1] = __float_as_uint(v1.x); af[im][3] = __float_as_uint(v1.y);
            }
#pragma unroll
            for (int in = 0; in < 4; in++) {
                int cn = wn * 32 + in * 8 + ly;
                float2 g = *(const float2*)(cB + cn * AST + kb + 2 * lx);
                float2 u = *(const float2*)(cB + (64 + cn) * AST + kb + 2 * lx);
                bg[in][0] = __float_as_uint(g.x); bg[in][1] = __float_as_uint(g.y);
                bu[in][0] = __float_as_uint(u.x); bu[in][1] = __float_as_uint(u.y);
            }
#pragma unroll
            for (int im = 0; im < 4; im++)
#pragma unroll
                for (int in = 0; in < 4; in++) {
                    mma8(accG[im][in], af[im], bg[in]);
                    mma8(accU[im][in], af[im], bu[in]);
                }
        }
    }

    // epilogue: out = rna(silu(g)*u), k-paired layout
    const int off0 = pk8(2 * lx);
#pragma unroll
    for (int im = 0; im < 4; im++) {
        int rr = bm * BM + wm * 64 + im * 16 + ly;
#pragma unroll
        for (int in = 0; in < 4; in++) {
            long long base = (long long)rr * ldc + bn * 64 + wn * 32 + in * 8;
            float* g = accG[im][in];
            float* u = accU[im][in];
            C[base + off0]                 = tf32r(silu_f(g[0]) * u[0]);
            C[base + off0 + 2]             = tf32r(silu_f(g[1]) * u[1]);
            C[base + 8LL * ldc + off0]     = tf32r(silu_f(g[2]) * u[2]);
            C[base + 8LL * ldc + off0 + 2] = tf32r(silu_f(g[3]) * u[3]);
        }
    }
}

// ---------------- phase 2: down GEMMs (templated expert/shared) ------------------
// CTA: 128 threads (2x2 warps). Tile: 128 x 128. Warp: 64 x 64.
template <bool EXPERT>
__global__ __launch_bounds__(128) void phase2_kernel(
    const float* __restrict__ hid, const float* __restrict__ dwT,
    const float* __restrict__ sh,  const float* __restrict__ sdw,
    float* __restrict__ pair, float* __restrict__ out)
{
    const int bid = blockIdx.x;
    const float *A, *B; const float* gate; float* C;
    int K, z = 0, bm, bn;
    if (EXPERT) {
        z = bid >> 8; int rem = bid & 255; bm = rem >> 3; bn = rem & 7;
        if (bm * BM >= d_cnt[z]) return;
        A = hid + (long long)z * NTOK * HDIM;
        K = HDIM;
        B = dwT + (long long)z * CDIM * HDIM + (long long)(bn * 128) * HDIM;
        C = pair + (long long)z * NTOK * CDIM;
        gate = d_gate[z];
    } else {
        bm = bid >> 3; bn = bid & 7;
        A = sh; K = HSDIM;
        B = sdw + (long long)(bn * 128) * HSDIM;
        C = out;
        gate = nullptr;
    }

    extern __shared__ __align__(16) float smem[];
    float* sA = smem;                   // [2][128][AST]
    float* sB = smem + 2 * STG;         // [2][128][AST]

    const int tid = threadIdx.x, lane = tid & 31, w = tid >> 5;
    const int ly = lane >> 2, lx = lane & 3;
    const int wm = w >> 1, wn = w & 1;  // 2 x 2 warps, each 64x64

    const int rbase = tid >> 3, kc = (tid & 7) * 4;
    const float* aBase = A + (long long)(bm * BM + rbase) * K;
    const float* bBase = B + (long long)rbase * K;

    auto loadStage = [&](int st, int k0) {
        float* dA = sA + st * STG;
        float* dB = sB + st * STG;
#pragma unroll
        for (int c = 0; c < 8; c++) {
            int row = rbase + 16 * c;
            cp16(dA + row * AST + kc, aBase + (long long)(16 * c) * K + k0 + kc);
            cp16(dB + row * AST + kc, bBase + (long long)(16 * c) * K + k0 + kc);
        }
        asm volatile("cp.async.commit_group;");
    };

    float acc[4][8][4];
#pragma unroll
    for (int a = 0; a < 4; a++)
#pragma unroll
        for (int b = 0; b < 8; b++)
#pragma unroll
            for (int q = 0; q < 4; q++) acc[a][b][q] = 0.f;

    const int nk = K / BK;
    loadStage(0, 0);

    for (int kt = 0; kt < nk; kt++) {
        const int st = kt & 1;
        asm volatile("cp.async.wait_group 0;");
        __syncthreads();
        if (kt + 1 < nk) loadStage((kt + 1) & 1, (kt + 1) * BK);

        const float* cA = sA + st * STG;
        const float* cB = sB + st * STG;
#pragma unroll
        for (int ks = 0; ks < 4; ks++) {
            const int kb = ks * 8;
            uint32_t af[4][4], bf[8][2];
#pragma unroll
            for (int im = 0; im < 4; im++) {
                int r = wm * 64 + im * 16;
                float2 v0 = *(const float2*)(cA + (r     + ly) * AST + kb + 2 * lx);
                float2 v1 = *(const float2*)(cA + (r + 8 + ly) * AST + kb + 2 * lx);
                af[im][0] = __float_as_uint(v0.x); af[im][2] = __float_as_uint(v0.y);
                af[im][1] = __float_as_uint(v1.x); af[im][3] = __float_as_uint(v1.y);
            }
#pragma unroll
            for (int in = 0; in < 8; in++) {
                int cn = wn * 64 + in * 8 + ly;
                float2 bb = *(const float2*)(cB + cn * AST + kb + 2 * lx);
                bf[in][0] = __float_as_uint(bb.x); bf[in][1] = __float_as_uint(bb.y);
            }
#pragma unroll
            for (int im = 0; im < 4; im++)
#pragma unroll
                for (int in = 0; in < 8; in++)
                    mma8(acc[im][in], af[im], bf[in]);
        }
    }

    // epilogue (canonical layout, float2 stores)
#pragma unroll
    for (int im = 0; im < 4; im++) {
        int rr = bm * BM + wm * 64 + im * 16 + ly;
        float s0 = gate ? gate[rr] : 1.f;
        float s1 = gate ? gate[rr + 8] : 1.f;
#pragma unroll
        for (int in = 0; in < 8; in++) {
            long long base = (long long)rr * CDIM + bn * 128 + wn * 64 + in * 8 + lx * 2;
            *(float2*)(C + base)              = make_float2(acc[im][in][0] * s0, acc[im][in][1] * s0);
            *(float2*)(C + base + 8LL * CDIM) = make_float2(acc[im][in][2] * s1, acc[im][in][3] * s1);
        }
    }
}

// ---------------- final combine: out += gated expert pair ----------------
__global__ void combine_kernel(float* __restrict__ out) {
    long long i = (long long)blockIdx.x * 256 + threadIdx.x;
    int t = (int)(i >> 8), j = (int)(i & 255);
    int es0 = d_eslot[t][0], es1 = d_eslot[t][1];
    float4 o  = ((float4*)out)[i];
    float4 p0 = ((const float4*)d_pair)[(long long)es0 * 256 + j];
    float4 p1 = ((const float4*)d_pair)[(long long)es1 * 256 + j];
    o.x += p0.x + p1.x; o.y += p0.y + p1.y;
    o.z += p0.z + p1.z; o.w += p0.w + p1.w;
    ((float4*)out)[i] = o;
}

// ---------------- launch ----------------
extern "C" void kernel_launch(void* const* d_in, const int* in_sizes, int n_in,
                              void* d_out, int out_size) {
    const float* x   = (const float*)d_in[0];
    const float* rw  = (const float*)d_in[1];
    const float* guw = (const float*)d_in[2];
    const float* dw  = (const float*)d_in[3];
    const float* sgw = (const float*)d_in[4];
    const float* suw = (const float*)d_in[5];
    const float* sdw = (const float*)d_in[6];
    float* out = (float*)d_out;

    void* a;
    float *p_hid, *p_pair, *p_sh, *p_xr, *p_guT, *p_dwT, *p_sgwr, *p_suwr, *p_sdwr;
    cudaGetSymbolAddress(&a, d_hid);  p_hid  = (float*)a;
    cudaGetSymbolAddress(&a, d_pair); p_pair = (float*)a;
    cudaGetSymbolAddress(&a, d_sh);   p_sh   = (float*)a;
    cudaGetSymbolAddress(&a, d_xr);   p_xr   = (float*)a;
    cudaGetSymbolAddress(&a, d_guT);  p_guT  = (float*)a;
    cudaGetSymbolAddress(&a, d_dwT);  p_dwT  = (float*)a;
    cudaGetSymbolAddress(&a, d_sgwr); p_sgwr = (float*)a;
    cudaGetSymbolAddress(&a, d_suwr); p_suwr = (float*)a;
    cudaGetSymbolAddress(&a, d_sdwr); p_sdwr = (float*)a;
    void* cntAddr; cudaGetSymbolAddress(&cntAddr, d_cnt);

    // lazily-created side streams + fork/join events (created on the FIRST,
    // uncaptured, correctness call; capture calls replay identical work)
    static cudaStream_t s1 = nullptr, s2 = nullptr;
    static cudaEvent_t ev0 = nullptr, evG = nullptr, evD = nullptr, evP = nullptr,
                       evR = nullptr, evS = nullptr;
    if (!s1) {
        cudaStreamCreateWithFlags(&s1, cudaStreamNonBlocking);
        cudaStreamCreateWithFlags(&s2, cudaStreamNonBlocking);
        cudaEventCreateWithFlags(&ev0, cudaEventDisableTiming);
        cudaEventCreateWithFlags(&evG, cudaEventDisableTiming);
        cudaEventCreateWithFlags(&evD, cudaEventDisableTiming);
        cudaEventCreateWithFlags(&evP, cudaEventDisableTiming);
        cudaEventCreateWithFlags(&evR, cudaEventDisableTiming);
        cudaEventCreateWithFlags(&evS, cudaEventDisableTiming);
        cudaFuncSetAttribute(phase1_kernel<true >, cudaFuncAttributeMaxDynamicSharedMemorySize, SMEMB);
        cudaFuncSetAttribute(phase1_kernel<false>, cudaFuncAttributeMaxDynamicSharedMemorySize, SMEMB);
        cudaFuncSetAttribute(phase2_kernel<true >, cudaFuncAttributeMaxDynamicSharedMemorySize, SMEMB);
        cudaFuncSetAttribute(phase2_kernel<false>, cudaFuncAttributeMaxDynamicSharedMemorySize, SMEMB);
    }

    // ---- fork point ----
    cudaEventRecord(ev0, 0);
    cudaStreamWaitEvent(s1, ev0, 0);

    // side stream s1: weight preprocessing (independent of router)
    transpose_rna_perm<<<dim3(2 * HDIM / 32, CDIM / 32, ENUM), dim3(32, 8), 0, s1>>>(guw, p_guT, CDIM, 2 * HDIM);
    cudaEventRecord(evG, s1);
    transpose_rna_perm<<<dim3(CDIM / 32, HDIM / 32, ENUM), dim3(32, 8), 0, s1>>>(dw, p_dwT, HDIM, CDIM);
    cudaEventRecord(evD, s1);
    round_perm3<<<dim3(HSDIM * CDIM / 8 / 256, 3), 256, 0, s1>>>(sgw, p_sgwr, suw, p_suwr, sdw, p_sdwr);
    cudaEventRecord(evP, s1);

    // main stream: router (emits k-paired tf32 x + routing tables)
    cudaMemsetAsync(cntAddr, 0, sizeof(int) * ENUM, 0);
    router_kernel<<<NTOK / 8, 256, 0, 0>>>(x, rw, p_xr);
    cudaEventRecord(evR, 0);

    // expert chain on main stream: p1e -> p2e
    cudaStreamWaitEvent(0, evG, 0);
    phase1_kernel<true><<<2048, 128, SMEMB, 0>>>(p_xr, p_guT, p_sgwr, p_suwr, p_hid, p_sh);
    cudaStreamWaitEvent(0, evD, 0);
    phase2_kernel<true><<<2048, 128, SMEMB, 0>>>(p_hid, p_dwT, p_sh, p_sdwr, p_pair, out);

    // shared chain on s2: p1s -> p2s (writes out base)
    cudaStreamWaitEvent(s2, evR, 0);
    cudaStreamWaitEvent(s2, evP, 0);
    phase1_kernel<false><<<1024, 128, SMEMB, s2>>>(p_xr, p_guT, p_sgwr, p_suwr, p_hid, p_sh);
    phase2_kernel<false><<<256, 128, SMEMB, s2>>>(p_hid, p_dwT, p_sh, p_sdwr, p_pair, out);
    cudaEventRecord(evS, s2);

    // ---- join: combine after both chains ----
    cudaStreamWaitEvent(0, evS, 0);
    combine_kernel<<<NTOK * CDIM / 4 / 256, 256, 0, 0>>>(out);

    (void)in_sizes; (void)n_in; (void)out_size;
}